// round 5
// baseline (speedup 1.0000x reference)
#include <cuda_runtime.h>

#define BB 256
#define TT 1024
#define DD 128
#define LL 16
#define OO 256

// ---- recurrence kernel geometry ----
#define NTHR 512            // 16 warps = 8 k-chunks x 2 o-halves
#define KPREG 10            // k-pairs (of 16) per (thread) kept in registers
#define KPSM  6             // k-pairs read from smem each step
#define RSM_STRIDE 208      // bytes/thread in Rsm: 24 u64 data + 2 pad (52 words -> conflict-free LDS.128)

#define PART_OFF 0                              // partial[8 chunks][2 batch][256 o]  = 16 KB
#define S_OFF    16384                          // state [2 batch][256]               = 2 KB
#define RSM_OFF  18432                          // Rsm: 512 * 208                     = 104 KB
#define SMEM_BYTES (RSM_OFF + NTHR * RSM_STRIDE)

__device__ float g_agg[(size_t)BB * TT * OO];

// ---------------------------------------------------------------------------
// Kernel 1: agg[b,t,o] = sum_l act_l( x[b,t,:]·sub_W[l,:] + sub_b[l] ) * agg_W[l,o]
// ---------------------------------------------------------------------------
__global__ void __launch_bounds__(256) act_agg_kernel(
    const float* __restrict__ x, const float* __restrict__ subW,
    const float* __restrict__ subb, const float* __restrict__ aggW)
{
    __shared__ float xs[16][DD];
    __shared__ float ws[LL][DD + 4];
    __shared__ float as_[16][LL + 1];

    const int tid = threadIdx.x;
    const size_t row0 = (size_t)blockIdx.x * 16;

    for (int i = tid; i < LL * DD; i += 256) ws[i / DD][i % DD] = subW[i];
    {
        const float4* xg = (const float4*)(x + row0 * DD);
        float4* xs4 = (float4*)&xs[0][0];
        for (int i = tid; i < 16 * DD / 4; i += 256) xs4[i] = xg[i];
    }
    __syncthreads();

    {
        const int l = tid & 15, r = tid >> 4;
        const float4* xr = (const float4*)&xs[r][0];
        const float4* wr = (const float4*)&ws[l][0];
        float acc = 0.f;
#pragma unroll
        for (int i = 0; i < DD / 4; i++) {
            float4 a = xr[i], b = wr[i];
            acc += a.x * b.x; acc += a.y * b.y; acc += a.z * b.z; acc += a.w * b.w;
        }
        acc += subb[l];
        float v;
        const int m = l & 3;
        if (m == 0)      v = tanhf(acc);
        else if (m == 1) v = fmaxf(acc, 0.f);
        else if (m == 2) v = 1.f / (1.f + expf(-acc));
        else             v = acc;
        as_[r][l] = v;
    }
    __syncthreads();

    {
        const int o = tid;
        float wcol[LL];
#pragma unroll
        for (int l = 0; l < LL; l++) wcol[l] = aggW[l * OO + o];
        float* outp = g_agg + row0 * OO + o;
#pragma unroll
        for (int r = 0; r < 16; r++) {
            float acc = 0.f;
#pragma unroll
            for (int l = 0; l < LL; l++) acc += as_[r][l] * wcol[l];
            outp[(size_t)r * OO] = acc;
        }
    }
}

// ---------------------------------------------------------------------------
// Kernel 2: recurrence, k-split across warps + smem partial reduction.
//   warp w: k-chunk c = w&7 (32 rows), o-half h = w>>3 (128 cols)
//   lane: 4 o-columns {h*128 + lane + 32j}, R as packed (k,k+1) f32x2 pairs
//   acc halves hold even-k / odd-k partial sums; combined at store.
// ---------------------------------------------------------------------------
#define FMA2(acc, a, b) asm("fma.rn.f32x2 %0, %1, %2, %0;" : "+l"(acc) : "l"(a), "l"(b))

__device__ __forceinline__ void lds_v2u64(unsigned long long& a, unsigned long long& b,
                                          unsigned int addr) {
    asm volatile("ld.shared.v2.u64 {%0, %1}, [%2];" : "=l"(a), "=l"(b) : "r"(addr));
}
__device__ __forceinline__ float lds_f32(unsigned int addr) {
    float v; asm volatile("ld.shared.f32 %0, [%1];" : "=f"(v) : "r"(addr)); return v;
}
__device__ __forceinline__ void sts_f32(unsigned int addr, float v) {
    asm volatile("st.shared.f32 [%0], %1;" :: "r"(addr), "f"(v));
}
__device__ __forceinline__ void sts_u64(unsigned int addr, unsigned long long v) {
    asm volatile("st.shared.u64 [%0], %1;" :: "r"(addr), "l"(v));
}

__global__ void __launch_bounds__(NTHR, 1) recur_kernel(const float* __restrict__ R,
                                                        float* __restrict__ out)
{
    extern __shared__ unsigned char dyn[];
    unsigned int sm;
    asm("{ .reg .u64 t0; cvta.to.shared.u64 t0, %1; cvt.u32.u64 %0, t0; }"
        : "=r"(sm) : "l"(dyn));

    const int tid  = threadIdx.x;
    const int lane = tid & 31;
    const int w    = tid >> 5;
    const int c    = w & 7;       // k-chunk (rows 32c..32c+31 of R)
    const int h    = w >> 3;      // o-half
    const int b0   = blockIdx.x * 2;

    // ---- R column pairs into registers: Rp[i*4+j] = (R[k,o_j], R[k+1,o_j]), k = 32c+2i
    unsigned long long Rp[KPREG * 4];
#pragma unroll
    for (int i = 0; i < KPREG; i++)
#pragma unroll
        for (int j = 0; j < 4; j++) {
            const int k = c * 32 + 2 * i;
            const int o = h * 128 + lane + 32 * j;
            float lo = R[(size_t)k * OO + o];
            float hi = R[(size_t)(k + 1) * OO + o];
            asm("mov.b64 %0, {%1, %2};" : "=l"(Rp[i * 4 + j]) : "f"(lo), "f"(hi));
        }

    // ---- remaining 6 k-pairs into per-thread smem rows (stride 208B -> conflict-free)
    const unsigned int rsm = sm + RSM_OFF + tid * RSM_STRIDE;
#pragma unroll
    for (int i = 0; i < KPSM; i++)
#pragma unroll
        for (int j = 0; j < 4; j++) {
            const int k = c * 32 + 2 * (KPREG + i);
            const int o = h * 128 + lane + 32 * j;
            float lo = R[(size_t)k * OO + o];
            float hi = R[(size_t)(k + 1) * OO + o];
            unsigned long long p;
            asm("mov.b64 %0, {%1, %2};" : "=l"(p) : "f"(lo), "f"(hi));
            sts_u64(rsm + (unsigned)(i * 4 + j) * 8, p);
        }

    // zero initial state (512 floats = 2 batches x 256)
    sts_f32(sm + S_OFF + tid * 4, 0.f);

    // phase-2 identity: thread -> (output column ot, batch bt)
    const int ot = tid & 255;
    const int bt = tid >> 8;
    const float* aggp = g_agg + ((size_t)(b0 + bt) * TT) * OO + ot;
    float*       outp = out   + ((size_t)(b0 + bt) * TT) * OO + ot;
    float a_cur = *aggp;

    const unsigned int sbase = sm + S_OFF + c * 128;                  // state chunk (batch A)
    const unsigned int pw = sm + PART_OFF + c * 2048 + h * 512 + lane * 4;  // partial write base
    const unsigned int pr = sm + PART_OFF + bt * 1024 + ot * 4;             // partial read base
    const unsigned int swadr = sm + S_OFF + bt * 1024 + ot * 4;             // state write addr

    __syncthreads();

    for (int t = 0; t < TT; t++) {
        float a_nxt = 0.f;
        if (t + 1 < TT) a_nxt = __ldg(aggp + OO);   // hidden under the FMA phase

        unsigned long long acc0 = 0, acc1 = 0, acc2 = 0, acc3 = 0,
                           acc4 = 0, acc5 = 0, acc6 = 0, acc7 = 0;

        // -------- phase 1: partial dot over this warp's 32 k-rows --------
#pragma unroll
        for (int ii = 0; ii < 5; ii++) {            // k-pairs 2ii, 2ii+1 from registers
            unsigned long long ax, ay, bx, by;
            lds_v2u64(ax, ay, sbase + ii * 16);           // batch A: (s_k,s_k+1),(s_k+2,s_k+3)
            lds_v2u64(bx, by, sbase + 1024 + ii * 16);    // batch B
            FMA2(acc0, ax, Rp[(2*ii)*4+0]);   FMA2(acc1, bx, Rp[(2*ii)*4+0]);
            FMA2(acc2, ax, Rp[(2*ii)*4+1]);   FMA2(acc3, bx, Rp[(2*ii)*4+1]);
            FMA2(acc4, ax, Rp[(2*ii)*4+2]);   FMA2(acc5, bx, Rp[(2*ii)*4+2]);
            FMA2(acc6, ax, Rp[(2*ii)*4+3]);   FMA2(acc7, bx, Rp[(2*ii)*4+3]);
            FMA2(acc0, ay, Rp[(2*ii+1)*4+0]); FMA2(acc1, by, Rp[(2*ii+1)*4+0]);
            FMA2(acc2, ay, Rp[(2*ii+1)*4+1]); FMA2(acc3, by, Rp[(2*ii+1)*4+1]);
            FMA2(acc4, ay, Rp[(2*ii+1)*4+2]); FMA2(acc5, by, Rp[(2*ii+1)*4+2]);
            FMA2(acc6, ay, Rp[(2*ii+1)*4+3]); FMA2(acc7, by, Rp[(2*ii+1)*4+3]);
        }
#pragma unroll
        for (int ii = 5; ii < 8; ii++) {            // k-pairs from smem R
            unsigned long long ax, ay, bx, by;
            lds_v2u64(ax, ay, sbase + ii * 16);
            lds_v2u64(bx, by, sbase + 1024 + ii * 16);
            unsigned long long r0, r1, r2, r3;
            lds_v2u64(r0, r1, rsm + (2*ii - 10) * 32);
            lds_v2u64(r2, r3, rsm + (2*ii - 10) * 32 + 16);
            FMA2(acc0, ax, r0); FMA2(acc1, bx, r0);
            FMA2(acc2, ax, r1); FMA2(acc3, bx, r1);
            FMA2(acc4, ax, r2); FMA2(acc5, bx, r2);
            FMA2(acc6, ax, r3); FMA2(acc7, bx, r3);
            lds_v2u64(r0, r1, rsm + (2*ii - 9) * 32);
            lds_v2u64(r2, r3, rsm + (2*ii - 9) * 32 + 16);
            FMA2(acc0, ay, r0); FMA2(acc1, by, r0);
            FMA2(acc2, ay, r1); FMA2(acc3, by, r1);
            FMA2(acc4, ay, r2); FMA2(acc5, by, r2);
            FMA2(acc6, ay, r3); FMA2(acc7, by, r3);
        }

        // combine even/odd-k halves, store 8 partials (conflict-free STS.32)
        {
            float x, y;
            asm("mov.b64 {%0,%1}, %2;" : "=f"(x), "=f"(y) : "l"(acc0)); sts_f32(pw + 0*1024 + 0*128, x + y);
            asm("mov.b64 {%0,%1}, %2;" : "=f"(x), "=f"(y) : "l"(acc1)); sts_f32(pw + 1*1024 + 0*128, x + y);
            asm("mov.b64 {%0,%1}, %2;" : "=f"(x), "=f"(y) : "l"(acc2)); sts_f32(pw + 0*1024 + 1*128, x + y);
            asm("mov.b64 {%0,%1}, %2;" : "=f"(x), "=f"(y) : "l"(acc3)); sts_f32(pw + 1*1024 + 1*128, x + y);
            asm("mov.b64 {%0,%1}, %2;" : "=f"(x), "=f"(y) : "l"(acc4)); sts_f32(pw + 0*1024 + 2*128, x + y);
            asm("mov.b64 {%0,%1}, %2;" : "=f"(x), "=f"(y) : "l"(acc5)); sts_f32(pw + 1*1024 + 2*128, x + y);
            asm("mov.b64 {%0,%1}, %2;" : "=f"(x), "=f"(y) : "l"(acc6)); sts_f32(pw + 0*1024 + 3*128, x + y);
            asm("mov.b64 {%0,%1}, %2;" : "=f"(x), "=f"(y) : "l"(acc7)); sts_f32(pw + 1*1024 + 3*128, x + y);
        }
        __syncthreads();

        // -------- phase 2: reduce 8 chunk-partials, add agg, publish state + output
        float red = a_cur;
#pragma unroll
        for (int c2 = 0; c2 < 8; c2++) red += lds_f32(pr + c2 * 2048);
        sts_f32(swadr, red);
        *outp = red;

        a_cur = a_nxt;
        aggp += OO;
        outp += OO;
        __syncthreads();
    }
}

// ---------------------------------------------------------------------------
extern "C" void kernel_launch(void* const* d_in, const int* in_sizes, int n_in,
                              void* d_out, int out_size)
{
    const float* x    = (const float*)d_in[0];
    const float* subW = (const float*)d_in[1];
    const float* subb = (const float*)d_in[2];
    const float* aggW = (const float*)d_in[3];
    const float* R    = (const float*)d_in[4];
    float* out = (float*)d_out;

    cudaFuncSetAttribute(recur_kernel, cudaFuncAttributeMaxDynamicSharedMemorySize,
                         SMEM_BYTES);

    act_agg_kernel<<<(BB * TT) / 16, 256>>>(x, subW, subb, aggW);
    recur_kernel<<<BB / 2, NTHR, SMEM_BYTES>>>(R, out);
}

// round 7
// speedup vs baseline: 1.7834x; 1.7834x over previous
#include <cuda_runtime.h>

#define BB 256
#define TT 1024
#define DD 128
#define LL 16
#define OO 256

// ---- recurrence kernel geometry: 256 thr = 8 warps = 4 k-chunks x 2 o-halves
// thread: 64 k-rows x 4 o-cols. 48 k in registers (24 pairs), 16 k via smem (8 pairs).
#define NTHR 256
#define RSM_TSTRIDE 272     // bytes/thread in Rsm: 32 u64 data + 2 u64 pad

#define PART_OFF 0                        // partial[4 chunk][2 batch][256 o] = 8 KB
#define S_OFF    8192                     // state [2 buf][2 batch][256]      = 4 KB
#define RSM_OFF  12288                    // Rsm: 256 * 272 = 69632 B
#define SMEM_BYTES (RSM_OFF + NTHR * RSM_TSTRIDE)   // 81920 B

__device__ float g_agg[(size_t)BB * TT * OO];

// ---------------------------------------------------------------------------
// Kernel 1: agg[b,t,o] = sum_l act_l( x[b,t,:]·sub_W[l,:] + sub_b[l] ) * agg_W[l,o]
// ---------------------------------------------------------------------------
__global__ void __launch_bounds__(256) act_agg_kernel(
    const float* __restrict__ x, const float* __restrict__ subW,
    const float* __restrict__ subb, const float* __restrict__ aggW)
{
    __shared__ float xs[16][DD];
    __shared__ float ws[LL][DD + 4];
    __shared__ float as_[16][LL + 1];

    const int tid = threadIdx.x;
    const size_t row0 = (size_t)blockIdx.x * 16;

    for (int i = tid; i < LL * DD; i += 256) ws[i / DD][i % DD] = subW[i];
    {
        const float4* xg = (const float4*)(x + row0 * DD);
        float4* xs4 = (float4*)&xs[0][0];
        for (int i = tid; i < 16 * DD / 4; i += 256) xs4[i] = xg[i];
    }
    __syncthreads();

    {
        const int l = tid & 15, r = tid >> 4;
        const float4* xr = (const float4*)&xs[r][0];
        const float4* wr = (const float4*)&ws[l][0];
        float acc = 0.f;
#pragma unroll
        for (int i = 0; i < DD / 4; i++) {
            float4 a = xr[i], b = wr[i];
            acc += a.x * b.x; acc += a.y * b.y; acc += a.z * b.z; acc += a.w * b.w;
        }
        acc += subb[l];
        float v;
        const int m = l & 3;
        if (m == 0)      v = tanhf(acc);
        else if (m == 1) v = fmaxf(acc, 0.f);
        else if (m == 2) v = 1.f / (1.f + expf(-acc));
        else             v = acc;
        as_[r][l] = v;
    }
    __syncthreads();

    {
        const int o = tid;
        float wcol[LL];
#pragma unroll
        for (int l = 0; l < LL; l++) wcol[l] = aggW[l * OO + o];
        float* outp = g_agg + row0 * OO + o;
#pragma unroll
        for (int r = 0; r < 16; r++) {
            float acc = 0.f;
#pragma unroll
            for (int l = 0; l < LL; l++) acc += as_[r][l] * wcol[l];
            outp[(size_t)r * OO] = acc;
        }
    }
}

// ---------------------------------------------------------------------------
// Kernel 2: recurrence s_t = agg_t + s_{t-1} @ R
//   warp w (of 8): k-chunk c = w&3 (rows 64c..64c+63), o-half h = w>>2
//   lane: o columns { h*128 + lane + 32j : j<4 }
//   R packed as (k,k+1) f32x2 pairs; acc f32x2 holds even/odd-k partials.
// ---------------------------------------------------------------------------
#define FMA2(acc, a, b) asm("fma.rn.f32x2 %0, %1, %2, %0;" : "+l"(acc) : "l"(a), "l"(b))

__device__ __forceinline__ void lds_v2u64(unsigned long long& a, unsigned long long& b,
                                          unsigned int addr) {
    asm volatile("ld.shared.v2.u64 {%0, %1}, [%2];" : "=l"(a), "=l"(b) : "r"(addr));
}
__device__ __forceinline__ float lds_f32(unsigned int addr) {
    float v; asm volatile("ld.shared.f32 %0, [%1];" : "=f"(v) : "r"(addr)); return v;
}
__device__ __forceinline__ void sts_f32(unsigned int addr, float v) {
    asm volatile("st.shared.f32 [%0], %1;" :: "r"(addr), "f"(v));
}
__device__ __forceinline__ void sts_u64(unsigned int addr, unsigned long long v) {
    asm volatile("st.shared.u64 [%0], %1;" :: "r"(addr), "l"(v));
}

__global__ void __launch_bounds__(NTHR, 1) recur_kernel(const float* __restrict__ R,
                                                        float* __restrict__ out)
{
    extern __shared__ unsigned char dyn[];
    unsigned int sm;
    asm("{ .reg .u64 t0; cvta.to.shared.u64 t0, %1; cvt.u32.u64 %0, t0; }"
        : "=r"(sm) : "l"(dyn));

    const int tid  = threadIdx.x;
    const int lane = tid & 31;
    const int w    = tid >> 5;
    const int c    = w & 3;        // k-chunk: rows 64c .. 64c+63
    const int h    = w >> 2;       // o-half
    const int b0   = blockIdx.x * 2;

    // ---- 24 k-pairs (48 rows) x 4 o-cols into registers
    unsigned long long Rp[24 * 4];
#pragma unroll
    for (int i = 0; i < 24; i++)
#pragma unroll
        for (int j = 0; j < 4; j++) {
            const int k = c * 64 + 2 * i;
            const int o = h * 128 + lane + 32 * j;
            float lo = R[(size_t)k * OO + o];
            float hi = R[(size_t)(k + 1) * OO + o];
            asm("mov.b64 %0, {%1, %2};" : "=l"(Rp[i * 4 + j]) : "f"(lo), "f"(hi));
        }

    // ---- 8 k-pairs (16 rows) x 4 o-cols into per-thread smem rows
    const unsigned int rsm = sm + RSM_OFF + tid * RSM_TSTRIDE;
#pragma unroll
    for (int i = 0; i < 8; i++)
#pragma unroll
        for (int j = 0; j < 4; j++) {
            const int k = c * 64 + 48 + 2 * i;
            const int o = h * 128 + lane + 32 * j;
            float lo = R[(size_t)k * OO + o];
            float hi = R[(size_t)(k + 1) * OO + o];
            unsigned long long p;
            asm("mov.b64 %0, {%1, %2};" : "=l"(p) : "f"(lo), "f"(hi));
            sts_u64(rsm + (unsigned)(i * 4 + j) * 8, p);
        }

    // zero initial state in buffer 0 (2 batches x 256)
    sts_f32(sm + S_OFF + 0 * 1024 + tid * 4, 0.f);
    sts_f32(sm + S_OFF + 1 * 1024 + tid * 4, 0.f);

    // phase-2 identity: thread -> output column o = tid, both batches
    const float* aggp0 = g_agg + ((size_t)b0       * TT) * OO + tid;
    const float* aggp1 = g_agg + ((size_t)(b0 + 1) * TT) * OO + tid;
    float*       outp0 = out   + ((size_t)b0       * TT) * OO + tid;
    float*       outp1 = out   + ((size_t)(b0 + 1) * TT) * OO + tid;
    float a0 = __ldg(aggp0), a1 = __ldg(aggp1);

    // addresses
    const unsigned int schunk = sm + S_OFF + c * 256;                 // + p*2048 (+1024 for batch B)
    const unsigned int pw     = sm + PART_OFF + c * 2048 + (h * 128 + lane) * 4;
    const unsigned int pr     = sm + PART_OFF + tid * 4;
    const unsigned int sw     = sm + S_OFF + tid * 4;                 // + (p^1)*2048 (+1024 batch B)

    __syncthreads();

    for (int t = 0; t < TT; t++) {
        const int p = t & 1;
        // prefetch NEXT timestep's agg (fixed-base indexed by t+1 — R6 bug was a
        // non-advancing pointer that re-read t=1 forever)
        float a0n = 0.f, a1n = 0.f;
        if (t + 1 < TT) {
            a0n = __ldg(aggp0 + (size_t)(t + 1) * OO);
            a1n = __ldg(aggp1 + (size_t)(t + 1) * OO);
        }

        const unsigned int sA = schunk + p * 2048;
        const unsigned int sB = sA + 1024;

        unsigned long long acc0 = 0, acc1 = 0, acc2 = 0, acc3 = 0,
                           acc4 = 0, acc5 = 0, acc6 = 0, acc7 = 0;

        // -------- phase 1a: 24 register k-pairs (2 pairs per iter) --------
#pragma unroll
        for (int ii = 0; ii < 12; ii++) {
            unsigned long long ax, ay, bx, by;
            lds_v2u64(ax, ay, sA + ii * 16);     // batch A pairs (2ii, 2ii+1)
            lds_v2u64(bx, by, sB + ii * 16);     // batch B
            FMA2(acc0, ax, Rp[(2*ii)*4+0]);   FMA2(acc4, bx, Rp[(2*ii)*4+0]);
            FMA2(acc1, ax, Rp[(2*ii)*4+1]);   FMA2(acc5, bx, Rp[(2*ii)*4+1]);
            FMA2(acc2, ax, Rp[(2*ii)*4+2]);   FMA2(acc6, bx, Rp[(2*ii)*4+2]);
            FMA2(acc3, ax, Rp[(2*ii)*4+3]);   FMA2(acc7, bx, Rp[(2*ii)*4+3]);
            FMA2(acc0, ay, Rp[(2*ii+1)*4+0]); FMA2(acc4, by, Rp[(2*ii+1)*4+0]);
            FMA2(acc1, ay, Rp[(2*ii+1)*4+1]); FMA2(acc5, by, Rp[(2*ii+1)*4+1]);
            FMA2(acc2, ay, Rp[(2*ii+1)*4+2]); FMA2(acc6, by, Rp[(2*ii+1)*4+2]);
            FMA2(acc3, ay, Rp[(2*ii+1)*4+3]); FMA2(acc7, by, Rp[(2*ii+1)*4+3]);
        }
        // -------- phase 1b: 8 smem k-pairs (2 pairs per iter) --------
#pragma unroll
        for (int q = 0; q < 4; q++) {
            unsigned long long ax, ay, bx, by;
            lds_v2u64(ax, ay, sA + (12 + q) * 16);
            lds_v2u64(bx, by, sB + (12 + q) * 16);
            unsigned long long r0, r1, r2, r3;
            lds_v2u64(r0, r1, rsm + (2*q) * 32);
            lds_v2u64(r2, r3, rsm + (2*q) * 32 + 16);
            FMA2(acc0, ax, r0); FMA2(acc4, bx, r0);
            FMA2(acc1, ax, r1); FMA2(acc5, bx, r1);
            FMA2(acc2, ax, r2); FMA2(acc6, bx, r2);
            FMA2(acc3, ax, r3); FMA2(acc7, bx, r3);
            lds_v2u64(r0, r1, rsm + (2*q+1) * 32);
            lds_v2u64(r2, r3, rsm + (2*q+1) * 32 + 16);
            FMA2(acc0, ay, r0); FMA2(acc4, by, r0);
            FMA2(acc1, ay, r1); FMA2(acc5, by, r1);
            FMA2(acc2, ay, r2); FMA2(acc6, by, r2);
            FMA2(acc3, ay, r3); FMA2(acc7, by, r3);
        }

        // combine even/odd-k halves, store 8 partials (coalesced STS.32)
        {
            float x, y;
            asm("mov.b64 {%0,%1}, %2;" : "=f"(x), "=f"(y) : "l"(acc0)); sts_f32(pw + 0*1024 + 0*128, x + y);
            asm("mov.b64 {%0,%1}, %2;" : "=f"(x), "=f"(y) : "l"(acc1)); sts_f32(pw + 0*1024 + 1*128, x + y);
            asm("mov.b64 {%0,%1}, %2;" : "=f"(x), "=f"(y) : "l"(acc2)); sts_f32(pw + 0*1024 + 2*128, x + y);
            asm("mov.b64 {%0,%1}, %2;" : "=f"(x), "=f"(y) : "l"(acc3)); sts_f32(pw + 0*1024 + 3*128, x + y);
            asm("mov.b64 {%0,%1}, %2;" : "=f"(x), "=f"(y) : "l"(acc4)); sts_f32(pw + 1*1024 + 0*128, x + y);
            asm("mov.b64 {%0,%1}, %2;" : "=f"(x), "=f"(y) : "l"(acc5)); sts_f32(pw + 1*1024 + 1*128, x + y);
            asm("mov.b64 {%0,%1}, %2;" : "=f"(x), "=f"(y) : "l"(acc6)); sts_f32(pw + 1*1024 + 2*128, x + y);
            asm("mov.b64 {%0,%1}, %2;" : "=f"(x), "=f"(y) : "l"(acc7)); sts_f32(pw + 1*1024 + 3*128, x + y);
        }
        __syncthreads();

        // -------- phase 2: reduce 4 chunk-partials per (o,batch), publish --------
        float r0 = a0 + lds_f32(pr + 0*2048)
                      + lds_f32(pr + 1*2048)
                      + lds_f32(pr + 2*2048)
                      + lds_f32(pr + 3*2048);
        float r1 = a1 + lds_f32(pr + 0*2048 + 1024)
                      + lds_f32(pr + 1*2048 + 1024)
                      + lds_f32(pr + 2*2048 + 1024)
                      + lds_f32(pr + 3*2048 + 1024);
        const unsigned int swp = sw + (p ^ 1) * 2048;
        sts_f32(swp, r0);
        sts_f32(swp + 1024, r1);
        outp0[(size_t)t * OO] = r0;
        outp1[(size_t)t * OO] = r1;

        a0 = a0n; a1 = a1n;
        __syncthreads();
    }
}

// ---------------------------------------------------------------------------
extern "C" void kernel_launch(void* const* d_in, const int* in_sizes, int n_in,
                              void* d_out, int out_size)
{
    const float* x    = (const float*)d_in[0];
    const float* subW = (const float*)d_in[1];
    const float* subb = (const float*)d_in[2];
    const float* aggW = (const float*)d_in[3];
    const float* R    = (const float*)d_in[4];
    float* out = (float*)d_out;

    cudaFuncSetAttribute(recur_kernel, cudaFuncAttributeMaxDynamicSharedMemorySize,
                         SMEM_BYTES);

    act_agg_kernel<<<(BB * TT) / 16, 256>>>(x, subW, subb, aggW);
    recur_kernel<<<BB / 2, NTHR, SMEM_BYTES>>>(R, out);
}